// round 15
// baseline (speedup 1.0000x reference)
#include <cuda_runtime.h>

// Potential_6347961663538 — Gaussian form-factor splatting onto a 128x128 grid.
//
// out[b,i,j] = sum_a sum_f (ff_a·4π/ff_b)[a,f] *
//              exp(-π·(4π/ff_b)[a,f] · ((j-64-c0[b,a])² + (i-64-c1[b,a])²))
//
// ALGORITHM: π·invb = 4π²/ff_b >= 19.74 (ff_b in [0.5,2]), so any term with
// per-axis |d| > 3.5 underflows fp32 exp to exactly 0 — identical to the
// zeros the reference itself adds. A 7x7 window around round(coord)
// reproduces every nonzero fp32 term: 671M dense terms -> ~401K (~1700x).
//
// FINAL CONFIG (R15 = R12/R13, best measured): warp-per-atom scatter,
// 1024 blocks x 256 threads (occ ~70% — R14 showed halving warp count for
// per-warp amortization loses more latency-hiding than it gains). Lanes 0-4
// build per-form-factor constants once (one divide each; sign and log2e
// pre-folded for raw EX2) and broadcast via SHFL. Each lane owns 2 window
// pixels; 5x ex2(p2_f·(dx²+dy²)) inline; REDG scatter (L2 same-address
// reductions pipeline — contention measured as a non-issue).
// Job-1 pixel ids 49..63 have row distance >=3.5 -> s underflows to exactly
// 0.0f and the s!=0 predicate rejects, so no explicit range guard is needed.
//
// CONVERGENCE: 14 rounds of evidence show bench total = max(floor, kernel +
// ~1.2us) with floor ≈ 8.5-8.7us (±0.25 noise), invariant to graph node
// count and kernel body below ~7us. This config produced the best total
// (8.48) and best kernel (5.25) of the session.

#define SIDELEN 128
#define NATOM   2048
#define NB      4
#define NF      5
#define RAD     3
#define WIN     7
#define WPB     8            // warps per block

__device__ __forceinline__ float ex2_approx(float x) {
    float r;
    asm("ex2.approx.f32 %0, %1;" : "=f"(r) : "f"(x));
    return r;
}

__global__ void __launch_bounds__(WPB * 32) potential_scatter_kernel(
    const float* __restrict__ coords,   // [NB, NATOM, 3]
    const float* __restrict__ ff_a,     // [NATOM, NF]
    const float* __restrict__ ff_b,     // [NATOM, NF]
    float* __restrict__ out)            // [NB, SIDELEN, SIDELEN]
{
    const int warp = blockIdx.x * WPB + (threadIdx.x >> 5);  // = b*NATOM + a
    const int lane = threadIdx.x & 31;
    const int b = warp >> 11;
    const int a = warp & (NATOM - 1);

    // Lanes 0..4: one form factor each, one divide each.
    float p2 = 0.0f, cf = 0.0f;
    if (lane < NF) {
        const float inv = __fdividef(1.0f, __ldg(&ff_b[a * NF + lane]));
        p2 = -56.9553183f * inv;                      // -(4π²·log2e)/ff_b
        cf = __ldg(&ff_a[a * NF + lane]) * 12.56637061f * inv;  // ff_a·4π/ff_b
    }
    const float p20 = __shfl_sync(0xffffffffu, p2, 0);
    const float p21 = __shfl_sync(0xffffffffu, p2, 1);
    const float p22 = __shfl_sync(0xffffffffu, p2, 2);
    const float p23 = __shfl_sync(0xffffffffu, p2, 3);
    const float p24 = __shfl_sync(0xffffffffu, p2, 4);
    const float cf0 = __shfl_sync(0xffffffffu, cf, 0);
    const float cf1 = __shfl_sync(0xffffffffu, cf, 1);
    const float cf2 = __shfl_sync(0xffffffffu, cf, 2);
    const float cf3 = __shfl_sync(0xffffffffu, cf, 3);
    const float cf4 = __shfl_sync(0xffffffffu, cf, 4);

    const float c0 = __ldg(&coords[warp * 3 + 0]);   // maps to j (fast axis)
    const float c1 = __ldg(&coords[warp * 3 + 1]);   // maps to i (slow axis)
    const int jc = __float2int_rn(c0);
    const int ic = __float2int_rn(c1);
    const float fx = (float)(jc - RAD) - c0;         // dx at window col 0
    const float fy = (float)(ic - RAD) - c1;         // dy at window row 0
    const int jb = jc + SIDELEN / 2 - RAD;
    const int ib = ic + SIDELEN / 2 - RAD;
    float* outb = out + (b << 14);

    // Two window pixels per lane: p = lane and lane+32.
    const int wi0 = lane / WIN, wj0 = lane - wi0 * WIN;
    const int pp  = lane + 32;
    const int wi1 = pp / WIN,   wj1 = pp - wi1 * WIN;   // rows>=7 underflow

    {
        const float dx = fx + (float)wj0, dy = fy + (float)wi0;
        const float dd = fmaf(dx, dx, dy * dy);
        float s =            cf0 * ex2_approx(p20 * dd);
        s = fmaf(cf1, ex2_approx(p21 * dd), s);
        s = fmaf(cf2, ex2_approx(p22 * dd), s);
        s = fmaf(cf3, ex2_approx(p23 * dd), s);
        s = fmaf(cf4, ex2_approx(p24 * dd), s);
        const int i = ib + wi0, j = jb + wj0;
        if ((unsigned)i < SIDELEN && (unsigned)j < SIDELEN && s != 0.0f)
            atomicAdd(&outb[(i << 7) + j], s);
    }
    {
        const float dx = fx + (float)wj1, dy = fy + (float)wi1;
        const float dd = fmaf(dx, dx, dy * dy);
        float s =            cf0 * ex2_approx(p20 * dd);
        s = fmaf(cf1, ex2_approx(p21 * dd), s);
        s = fmaf(cf2, ex2_approx(p22 * dd), s);
        s = fmaf(cf3, ex2_approx(p23 * dd), s);
        s = fmaf(cf4, ex2_approx(p24 * dd), s);
        const int i = ib + wi1, j = jb + wj1;
        if ((unsigned)i < SIDELEN && (unsigned)j < SIDELEN && s != 0.0f)
            atomicAdd(&outb[(i << 7) + j], s);
    }
}

extern "C" void kernel_launch(void* const* d_in, const int* in_sizes, int n_in,
                              void* d_out, int out_size) {
    const float* coords = (const float*)d_in[0];
    const float* ff_a   = (const float*)d_in[1];
    const float* ff_b   = (const float*)d_in[2];
    float* out = (float*)d_out;

    cudaMemsetAsync(out, 0, (size_t)out_size * sizeof(float));
    potential_scatter_kernel<<<(NB * NATOM) / WPB, WPB * 32>>>(coords, ff_a, ff_b, out);
}

// round 16
// speedup vs baseline: 1.0588x; 1.0588x over previous
#include <cuda_runtime.h>

// Potential_6347961663538 — Gaussian form-factor splatting onto a 128x128 grid.
//
// out[b,i,j] = sum_a sum_f (ff_a·4π/ff_b)[a,f] *
//              exp(-π·(4π/ff_b)[a,f] · ((j-64-c0[b,a])² + (i-64-c1[b,a])²))
//
// ALGORITHM: π·invb = 4π²/ff_b >= 19.74 (ff_b in [0.5,2]), so any term with
// per-axis |d| > 3.5 underflows fp32 exp to exactly 0 — identical to the
// zeros the reference itself adds. A 7x7 window around round(coord)
// reproduces every nonzero fp32 term: 671M dense terms -> ~401K (~1700x).
//
// R16: same warp-per-atom body as the best-measured config (R12/R13), but
// 512 blocks x 512 threads instead of 1024 x 256 — SAME 8192 warps (R14
// proved halving warp count loses latency hiding), HALF the CTAs. CTA
// distribution/launch ramp is per-CTA and is the dominant fixed cost of a
// ~5.3us kernel whose compute is ~1.5us; occupancy is unchanged.
//
// Context: bench total = max(replay-floor, kernel + ~1.2us); floor draws
// observed in 8.48-9.22us for identical ~5.3us kernels. Cutting kernel time
// is the only way to shift the total distribution left.

#define SIDELEN 128
#define NATOM   2048
#define NB      4
#define NF      5
#define RAD     3
#define WIN     7
#define WPB     16           // warps per block (512 threads)

__device__ __forceinline__ float ex2_approx(float x) {
    float r;
    asm("ex2.approx.f32 %0, %1;" : "=f"(r) : "f"(x));
    return r;
}

__global__ void __launch_bounds__(WPB * 32) potential_scatter_kernel(
    const float* __restrict__ coords,   // [NB, NATOM, 3]
    const float* __restrict__ ff_a,     // [NATOM, NF]
    const float* __restrict__ ff_b,     // [NATOM, NF]
    float* __restrict__ out)            // [NB, SIDELEN, SIDELEN]
{
    const int warp = blockIdx.x * WPB + (threadIdx.x >> 5);  // = b*NATOM + a
    const int lane = threadIdx.x & 31;
    const int b = warp >> 11;
    const int a = warp & (NATOM - 1);

    // Lanes 0..4: one form factor each, one divide each.
    float p2 = 0.0f, cf = 0.0f;
    if (lane < NF) {
        const float inv = __fdividef(1.0f, __ldg(&ff_b[a * NF + lane]));
        p2 = -56.9553183f * inv;                      // -(4π²·log2e)/ff_b
        cf = __ldg(&ff_a[a * NF + lane]) * 12.56637061f * inv;  // ff_a·4π/ff_b
    }
    const float p20 = __shfl_sync(0xffffffffu, p2, 0);
    const float p21 = __shfl_sync(0xffffffffu, p2, 1);
    const float p22 = __shfl_sync(0xffffffffu, p2, 2);
    const float p23 = __shfl_sync(0xffffffffu, p2, 3);
    const float p24 = __shfl_sync(0xffffffffu, p2, 4);
    const float cf0 = __shfl_sync(0xffffffffu, cf, 0);
    const float cf1 = __shfl_sync(0xffffffffu, cf, 1);
    const float cf2 = __shfl_sync(0xffffffffu, cf, 2);
    const float cf3 = __shfl_sync(0xffffffffu, cf, 3);
    const float cf4 = __shfl_sync(0xffffffffu, cf, 4);

    const float c0 = __ldg(&coords[warp * 3 + 0]);   // maps to j (fast axis)
    const float c1 = __ldg(&coords[warp * 3 + 1]);   // maps to i (slow axis)
    const int jc = __float2int_rn(c0);
    const int ic = __float2int_rn(c1);
    const float fx = (float)(jc - RAD) - c0;         // dx at window col 0
    const float fy = (float)(ic - RAD) - c1;         // dy at window row 0
    const int jb = jc + SIDELEN / 2 - RAD;
    const int ib = ic + SIDELEN / 2 - RAD;
    float* outb = out + (b << 14);

    // Two window pixels per lane: p = lane and lane+32.
    const int wi0 = lane / WIN, wj0 = lane - wi0 * WIN;
    const int pp  = lane + 32;
    const int wi1 = pp / WIN,   wj1 = pp - wi1 * WIN;   // rows>=7 underflow to 0

    {
        const float dx = fx + (float)wj0, dy = fy + (float)wi0;
        const float dd = fmaf(dx, dx, dy * dy);
        float s =            cf0 * ex2_approx(p20 * dd);
        s = fmaf(cf1, ex2_approx(p21 * dd), s);
        s = fmaf(cf2, ex2_approx(p22 * dd), s);
        s = fmaf(cf3, ex2_approx(p23 * dd), s);
        s = fmaf(cf4, ex2_approx(p24 * dd), s);
        const int i = ib + wi0, j = jb + wj0;
        if ((unsigned)i < SIDELEN && (unsigned)j < SIDELEN && s != 0.0f)
            atomicAdd(&outb[(i << 7) + j], s);
    }
    {
        const float dx = fx + (float)wj1, dy = fy + (float)wi1;
        const float dd = fmaf(dx, dx, dy * dy);
        float s =            cf0 * ex2_approx(p20 * dd);
        s = fmaf(cf1, ex2_approx(p21 * dd), s);
        s = fmaf(cf2, ex2_approx(p22 * dd), s);
        s = fmaf(cf3, ex2_approx(p23 * dd), s);
        s = fmaf(cf4, ex2_approx(p24 * dd), s);
        const int i = ib + wi1, j = jb + wj1;
        if ((unsigned)i < SIDELEN && (unsigned)j < SIDELEN && s != 0.0f)
            atomicAdd(&outb[(i << 7) + j], s);
    }
}

extern "C" void kernel_launch(void* const* d_in, const int* in_sizes, int n_in,
                              void* d_out, int out_size) {
    const float* coords = (const float*)d_in[0];
    const float* ff_a   = (const float*)d_in[1];
    const float* ff_b   = (const float*)d_in[2];
    float* out = (float*)d_out;

    cudaMemsetAsync(out, 0, (size_t)out_size * sizeof(float));
    potential_scatter_kernel<<<(NB * NATOM) / WPB, WPB * 32>>>(coords, ff_a, ff_b, out);
}

// round 17
// speedup vs baseline: 1.0627x; 1.0037x over previous
#include <cuda_runtime.h>

// Potential_6347961663538 — Gaussian form-factor splatting onto a 128x128 grid.
//
// out[b,i,j] = sum_a sum_f (ff_a·4π/ff_b)[a,f] *
//              exp(-π·(4π/ff_b)[a,f] · ((j-64-c0[b,a])² + (i-64-c1[b,a])²))
//
// ALGORITHM: π·invb = 4π²/ff_b >= 19.74 (ff_b in [0.5,2]), so any term with
// per-axis |d| > 3.5 underflows fp32 exp to exactly 0 — identical to the
// zeros the reference itself adds. A 7x7 window around round(coord)
// reproduces every nonzero fp32 term: the dense B·A·P·5 = 671M-term sum
// collapses to ~401K window terms (~1700x less work). This is the win that
// took the problem from a ~1.3-5ms dense roofline to a ~5us kernel.
//
// KERNEL (session-best, R12/R13): warp-per-atom scatter, 1024 blocks x 256
// threads (occ ~70%). Lanes 0-4 build per-form-factor constants once (one
// divide each: p2 = -(4π²·log2e)/ff_b, sign+log2e pre-folded for raw EX2;
// coef = ff_a·4π/ff_b), broadcast via SHFL. Each lane owns 2 window pixels,
// computes 5x ex2(p2_f·(dx²+dy²)) inline, scatters with REDG (L2
// same-address reductions pipeline at ~0.854 cyc/lane — measured non-issue).
//
// CONVERGENCE EVIDENCE (16 rounds):
//  - kernel time pinned ~5.3us across all sane shapes (1024x256, 512x512,
//    512x256/2-atom, fused 128x512): launch/drain fixed cost ~3.8us +
//    compute ~1.5us; instruction-count cuts of 4x moved it <0.2us.
//  - bench total = max(replay-floor-draw, kernel + 0.13us); floor draws
//    observed 8.48-9.22us (median ~8.7) for identical binaries — host-side
//    graph-submit bound, invariant to node count and kernel body.
//  - alternatives all measured worse: gathers 10.9-25us (row-density tail),
//    smem-image 6.7us (occupancy), grid-barrier fusion 6.4-8.4us (skew spin).
// This source produced the session-best total (8.48) and kernel (5.248).

#define SIDELEN 128
#define NATOM   2048
#define NB      4
#define NF      5
#define RAD     3
#define WIN     7
#define WPB     8            // warps per block

__device__ __forceinline__ float ex2_approx(float x) {
    float r;
    asm("ex2.approx.f32 %0, %1;" : "=f"(r) : "f"(x));
    return r;
}

__global__ void __launch_bounds__(WPB * 32) potential_scatter_kernel(
    const float* __restrict__ coords,   // [NB, NATOM, 3]
    const float* __restrict__ ff_a,     // [NATOM, NF]
    const float* __restrict__ ff_b,     // [NATOM, NF]
    float* __restrict__ out)            // [NB, SIDELEN, SIDELEN]
{
    const int warp = blockIdx.x * WPB + (threadIdx.x >> 5);  // = b*NATOM + a
    const int lane = threadIdx.x & 31;
    const int b = warp >> 11;
    const int a = warp & (NATOM - 1);

    // Lanes 0..4: one form factor each, one divide each.
    float p2 = 0.0f, cf = 0.0f;
    if (lane < NF) {
        const float inv = __fdividef(1.0f, __ldg(&ff_b[a * NF + lane]));
        p2 = -56.9553183f * inv;                      // -(4π²·log2e)/ff_b
        cf = __ldg(&ff_a[a * NF + lane]) * 12.56637061f * inv;  // ff_a·4π/ff_b
    }
    const float p20 = __shfl_sync(0xffffffffu, p2, 0);
    const float p21 = __shfl_sync(0xffffffffu, p2, 1);
    const float p22 = __shfl_sync(0xffffffffu, p2, 2);
    const float p23 = __shfl_sync(0xffffffffu, p2, 3);
    const float p24 = __shfl_sync(0xffffffffu, p2, 4);
    const float cf0 = __shfl_sync(0xffffffffu, cf, 0);
    const float cf1 = __shfl_sync(0xffffffffu, cf, 1);
    const float cf2 = __shfl_sync(0xffffffffu, cf, 2);
    const float cf3 = __shfl_sync(0xffffffffu, cf, 3);
    const float cf4 = __shfl_sync(0xffffffffu, cf, 4);

    const float c0 = __ldg(&coords[warp * 3 + 0]);   // maps to j (fast axis)
    const float c1 = __ldg(&coords[warp * 3 + 1]);   // maps to i (slow axis)
    const int jc = __float2int_rn(c0);
    const int ic = __float2int_rn(c1);
    const float fx = (float)(jc - RAD) - c0;         // dx at window col 0
    const float fy = (float)(ic - RAD) - c1;         // dy at window row 0
    const int jb = jc + SIDELEN / 2 - RAD;
    const int ib = ic + SIDELEN / 2 - RAD;
    float* outb = out + (b << 14);

    // Two window pixels per lane: p = lane and lane+32 (49 total).
    const int wi0 = lane / WIN, wj0 = lane - wi0 * WIN;
    const int pp  = lane + 32;
    const int wi1 = pp / WIN,   wj1 = pp - wi1 * WIN;

    {
        const float dx = fx + (float)wj0, dy = fy + (float)wi0;
        const float dd = fmaf(dx, dx, dy * dy);
        float s =            cf0 * ex2_approx(p20 * dd);
        s = fmaf(cf1, ex2_approx(p21 * dd), s);
        s = fmaf(cf2, ex2_approx(p22 * dd), s);
        s = fmaf(cf3, ex2_approx(p23 * dd), s);
        s = fmaf(cf4, ex2_approx(p24 * dd), s);
        const int i = ib + wi0, j = jb + wj0;
        if ((unsigned)i < SIDELEN && (unsigned)j < SIDELEN && s != 0.0f)
            atomicAdd(&outb[(i << 7) + j], s);
    }
    if (pp < WIN * WIN) {
        const float dx = fx + (float)wj1, dy = fy + (float)wi1;
        const float dd = fmaf(dx, dx, dy * dy);
        float s =            cf0 * ex2_approx(p20 * dd);
        s = fmaf(cf1, ex2_approx(p21 * dd), s);
        s = fmaf(cf2, ex2_approx(p22 * dd), s);
        s = fmaf(cf3, ex2_approx(p23 * dd), s);
        s = fmaf(cf4, ex2_approx(p24 * dd), s);
        const int i = ib + wi1, j = jb + wj1;
        if ((unsigned)i < SIDELEN && (unsigned)j < SIDELEN && s != 0.0f)
            atomicAdd(&outb[(i << 7) + j], s);
    }
}

extern "C" void kernel_launch(void* const* d_in, const int* in_sizes, int n_in,
                              void* d_out, int out_size) {
    const float* coords = (const float*)d_in[0];
    const float* ff_a   = (const float*)d_in[1];
    const float* ff_b   = (const float*)d_in[2];
    float* out = (float*)d_out;

    cudaMemsetAsync(out, 0, (size_t)out_size * sizeof(float));
    potential_scatter_kernel<<<(NB * NATOM) / WPB, WPB * 32>>>(coords, ff_a, ff_b, out);
}